// round 10
// baseline (speedup 1.0000x reference)
#include <cuda_runtime.h>
#include <cuda_bf16.h>
#include <math.h>

#define BNUM 32
#define CLIPD 1024
#define OCN 512
#define KTOP 30
#define NROI (BNUM*KTOP)     // 960
#define NANCH 2304           // 16*16*9
#define FULLM 0xFFFFFFFFu

// ---------------- scratch (static device globals; no runtime alloc) -------------
__device__ float g_x[BNUM*256*OCN];          // conv output, layout [b*256+pos][oc]
__device__ float g_scores[BNUM*NANCH];
__device__ float g_boxes[BNUM*NANCH*4];
__device__ float g_rois[NROI*4];
__device__ int   g_valid[NROI];
__device__ float g_integral[BNUM*257*257];
__device__ int   g_labels[NROI];
__device__ float g_pooled[NROI*CLIPD];
__device__ float g_proj[NROI*256];
__device__ float g_li[NROI];
__device__ int   g_active[NROI];

// bf16 3-way splits of activations [b][pos][c] and weights [tap][oc][c]
__device__ __align__(16) unsigned short g_a0[BNUM*256*1024];
__device__ __align__(16) unsigned short g_a1[BNUM*256*1024];
__device__ __align__(16) unsigned short g_a2[BNUM*256*1024];
__device__ __align__(16) unsigned short g_w0[9*512*1024];
__device__ __align__(16) unsigned short g_w1[9*512*1024];
__device__ __align__(16) unsigned short g_w2[9*512*1024];

// anchor w/h for a = si*3+ri, scales {8,16,32}, ratios {0.5,1,2}
__constant__ float c_AW[9] = {5.656854249492381f, 8.f, 11.313708498984761f,
                              11.313708498984761f, 16.f, 22.627416997969522f,
                              22.627416997969522f, 32.f, 45.254833995939045f};
__constant__ float c_AH[9] = {11.313708498984761f, 8.f, 5.656854249492381f,
                              22.627416997969522f, 16.f, 11.313708498984761f,
                              45.254833995939045f, 32.f, 22.627416997969522f};

// ================= warp-level tensor core helpers (baseline PTX, sm_80+) =========
__device__ __forceinline__ unsigned smem_u32(const void* p) {
    unsigned a;
    asm("{ .reg .u64 tmp; cvta.to.shared.u64 tmp, %1; cvt.u32.u64 %0, tmp; }"
        : "=r"(a) : "l"(p));
    return a;
}
__device__ __forceinline__ void ldsm4(unsigned* r, unsigned addr) {
    asm volatile("ldmatrix.sync.aligned.m8n8.x4.shared.b16 {%0,%1,%2,%3}, [%4];"
        : "=r"(r[0]), "=r"(r[1]), "=r"(r[2]), "=r"(r[3]) : "r"(addr));
}
__device__ __forceinline__ void mma16816(float* d, const unsigned* a, const unsigned* b) {
    asm volatile(
        "mma.sync.aligned.m16n8k16.row.col.f32.bf16.bf16.f32 "
        "{%0,%1,%2,%3}, {%4,%5,%6,%7}, {%8,%9}, {%0,%1,%2,%3};"
        : "+f"(d[0]), "+f"(d[1]), "+f"(d[2]), "+f"(d[3])
        : "r"(a[0]), "r"(a[1]), "r"(a[2]), "r"(a[3]), "r"(b[0]), "r"(b[1]));
}

// ---------------- 0a. split activations fp32 -> 3x bf16 -------------------------
__device__ __forceinline__ void bsplit(float v, unsigned short& s0,
                                       unsigned short& s1, unsigned short& s2) {
    __nv_bfloat16 b0 = __float2bfloat16(v);
    float r = v - __bfloat162float(b0);
    __nv_bfloat16 b1 = __float2bfloat16(r);
    float r2 = r - __bfloat162float(b1);
    __nv_bfloat16 b2 = __float2bfloat16(r2);
    s0 = __bfloat16_as_ushort(b0);
    s1 = __bfloat16_as_ushort(b1);
    s2 = __bfloat16_as_ushort(b2);
}

__global__ __launch_bounds__(256) void split_act(const float* __restrict__ clip) {
    const size_t idx = (size_t)blockIdx.x * 256 + threadIdx.x;   // float4 index
    const size_t e = idx * 4;
    const int c4 = (int)(e & 1023);
    const int bp = (int)(e >> 10);
    const int b = bp >> 8, pos = bp & 255;
    const float4 v = *(const float4*)(clip + (size_t)(1 + pos)*32768 + b*1024 + c4);
    ushort4 u0, u1, u2;
    bsplit(v.x, u0.x, u1.x, u2.x);
    bsplit(v.y, u0.y, u1.y, u2.y);
    bsplit(v.z, u0.z, u1.z, u2.z);
    bsplit(v.w, u0.w, u1.w, u2.w);
    *(ushort4*)(g_a0 + e) = u0;
    *(ushort4*)(g_a1 + e) = u1;
    *(ushort4*)(g_a2 + e) = u2;
}

// ---------------- 0b. split weights [oc][c][tap] -> 3x bf16 [tap][oc][c] --------
__global__ __launch_bounds__(256) void split_w(const float* __restrict__ W) {
    const size_t idx = (size_t)blockIdx.x * 256 + threadIdx.x;   // [tap][oc][c]
    const int c = (int)(idx & 1023);
    const int oc = (int)((idx >> 10) & 511);
    const int tap = (int)(idx >> 19);
    const float v = W[((size_t)oc*1024 + c)*9 + tap];
    unsigned short s0, s1, s2;
    bsplit(v, s0, s1, s2);
    g_w0[idx] = s0; g_w1[idx] = s1; g_w2[idx] = s2;
}

// ---------------- 1. conv as implicit GEMM via mma.sync (bf16x3 split) ----------
// grid (8, 32): x = mh*4 + nt, y = b. CTA = 128 pos x 128 oc.
// 8 warps in 2x4; each warp owns 64x32 = 4x4 m16n8 tiles.
// A staged as 10x18 position halo per 32-channel chunk (all 9 taps read shifted
// windows via per-lane ldmatrix addressing). B staged per (tap, chunk).
// smem rows stride 80B -> 20-bank row offset -> conflict-free LDSM.
#define SA_SZ   (180*80)                 // 14400 B per split
#define SB_OFF  (3*SA_SZ)                // 43200
#define SB_SZ   (128*80)                 // 10240 B per split
#define CONV_SMEM (SB_OFF + 3*SB_SZ)     // 73920 B

__global__ __launch_bounds__(256, 2) void conv_mma_kernel(const float* __restrict__ bias) {
    extern __shared__ char cms[];
    const unsigned sbase = smem_u32(cms);
    const int t = threadIdx.x, lane = t & 31, wid = t >> 5;
    const int mh = blockIdx.x >> 2, nt = blockIdx.x & 3;
    const int b = blockIdx.y;
    const int wm = wid >> 2, wn = wid & 3;   // warps 2 (m) x 4 (n)
    const int R0 = mh * 8;                   // first image row of this half

    const unsigned short* AP[3] = {g_a0, g_a1, g_a2};
    const unsigned short* WP[3] = {g_w0, g_w1, g_w2};

    float acc[4][4][4];
    #pragma unroll
    for (int mt = 0; mt < 4; mt++)
        #pragma unroll
        for (int n = 0; n < 4; n++)
            #pragma unroll
            for (int q = 0; q < 4; q++) acc[mt][n][q] = 0.f;

    // per-lane ldmatrix geometry
    const int rw   = lane & 7;
    const int aRow8 = (lane >> 3) & 1;       // A: sel&1 -> +8 rows
    const int aK8   = lane >> 4;             // A: sel>>1 -> +8 k
    int lrA[4], lcA[4];                      // image row/col of this lane's A row
    #pragma unroll
    for (int mt = 0; mt < 4; mt++) {
        const int p = wm*64 + mt*16 + aRow8*8 + rw;
        lrA[mt] = p >> 4; lcA[mt] = p & 15;
    }
    const int bK8  = (lane >> 3) & 1;        // B: sel&1 -> +8 k
    const int bN8  = (lane >> 4);            // B: sel>>1 -> +8 n rows
    const unsigned bRowAddr = (unsigned)((wn*32 + bN8*8 + rw)*80 + bK8*16);

    for (int cb = 0; cb < 32; cb++) {
        const int c0 = cb * 32;
        __syncthreads();
        // stage A halo: 3 splits x 180 cells x 4 x 16B (zeros outside image)
        for (int idx = t; idx < 2160; idx += 256) {
            const int s = idx / 720, rem = idx % 720;
            const int cell = rem >> 2, q = rem & 3;
            const int hr = cell / 18, hc = cell % 18;
            const int ir = R0 - 1 + hr, jc = hc - 1;
            uint4 v = make_uint4(0u, 0u, 0u, 0u);
            if (ir >= 0 && ir < 16 && jc >= 0 && jc < 16)
                v = *(const uint4*)(AP[s] + ((size_t)(b*256 + ir*16 + jc)*1024 + c0 + q*8));
            *(uint4*)(cms + s*SA_SZ + cell*80 + q*16) = v;
        }
        for (int tap = 0; tap < 9; tap++) {
            const int di = tap/3 - 1, dj = tap%3 - 1;
            __syncthreads();   // A visible / prior B reads done
            // stage B: 3 splits x 128 oc rows x 4 x 16B
            for (int idx = t; idx < 1536; idx += 256) {
                const int s = idx >> 9, rem = idx & 511;
                const int row = rem >> 2, q = rem & 3;
                const uint4 v = *(const uint4*)(WP[s] +
                    ((size_t)(tap*512 + nt*128 + row)*1024 + c0 + q*8));
                *(uint4*)(cms + SB_OFF + s*SB_SZ + row*80 + q*16) = v;
            }
            __syncthreads();

            // A cell addresses for this tap (per m-tile)
            unsigned aAddr[4];
            #pragma unroll
            for (int mt = 0; mt < 4; mt++)
                aAddr[mt] = sbase +
                    (unsigned)(((lrA[mt] + di + 1)*18 + lcA[mt] + dj + 1)*80 + aK8*16);

            #pragma unroll
            for (int ks = 0; ks < 2; ks++) {
                const unsigned ko = (unsigned)(ks*32);
                #pragma unroll
                for (int s = 0; s < 3; s++) {
                    unsigned aF[4][4];
                    #pragma unroll
                    for (int mt = 0; mt < 4; mt++)
                        ldsm4(aF[mt], aAddr[mt] + s*SA_SZ + ko);
                    #pragma unroll
                    for (int tb = 0; tb < 3; tb++) {
                        if (s + tb >= 3) break;
                        unsigned bF[2][4];
                        #pragma unroll
                        for (int j = 0; j < 2; j++)
                            ldsm4(bF[j], sbase + SB_OFF + tb*SB_SZ +
                                         bRowAddr + (unsigned)(j*16*80) + ko);
                        #pragma unroll
                        for (int mt = 0; mt < 4; mt++)
                            #pragma unroll
                            for (int n = 0; n < 4; n++)
                                mma16816(acc[mt][n], aF[mt], &bF[n >> 1][(n & 1)*2]);
                    }
                }
            }
        }
    }

    // epilogue: bias + relu + store
    const int g = lane >> 2, tg = lane & 3;
    #pragma unroll
    for (int mt = 0; mt < 4; mt++) {
        const int pos0 = mh*128 + wm*64 + mt*16 + g;
        #pragma unroll
        for (int n = 0; n < 4; n++) {
            const int oc = nt*128 + wn*32 + n*8 + tg*2;
            const float2 bb = *(const float2*)&bias[oc];
            float2 o0, o1;
            o0.x = fmaxf(acc[mt][n][0] + bb.x, 0.f);
            o0.y = fmaxf(acc[mt][n][1] + bb.y, 0.f);
            o1.x = fmaxf(acc[mt][n][2] + bb.x, 0.f);
            o1.y = fmaxf(acc[mt][n][3] + bb.y, 0.f);
            *(float2*)&g_x[((size_t)(b*256 + pos0    ))*512 + oc] = o0;
            *(float2*)&g_x[((size_t)(b*256 + pos0 + 8))*512 + oc] = o1;
        }
    }
}

// ---------------- 2. cls/reg heads + decode + sigmoid ---------------------------
extern __shared__ float s_hw[];   // [45][512]
__global__ __launch_bounds__(256) void head_kernel(const float* __restrict__ cls_w,
                                                   const float* __restrict__ cls_b,
                                                   const float* __restrict__ reg_w,
                                                   const float* __restrict__ reg_b) {
    const int b = blockIdx.y, grp = blockIdx.x;
    const int t = threadIdx.x, w = t >> 5, lane = t & 31;
    __shared__ float ovs[32][48];

    for (int idx = t; idx < 45*512; idx += 256) {
        const int o = idx >> 9, k = idx & 511;
        s_hw[idx] = (o < 9) ? cls_w[o*512 + k] : reg_w[(o - 9)*512 + k];
    }

    float xr[4][16];
    #pragma unroll
    for (int pp = 0; pp < 4; pp++) {
        const size_t row = (size_t)(b*256 + grp*32 + w*4 + pp);
        #pragma unroll
        for (int q = 0; q < 16; q++)
            xr[pp][q] = g_x[row*512 + q*32 + lane];
    }
    __syncthreads();

    for (int o = 0; o < 45; o++) {
        const float* wr = &s_hw[o*512];
        float wv[16];
        #pragma unroll
        for (int q = 0; q < 16; q++) wv[q] = wr[q*32 + lane];
        #pragma unroll
        for (int pp = 0; pp < 4; pp++) {
            float s = 0.f;
            #pragma unroll
            for (int q = 0; q < 16; q++) s = fmaf(xr[pp][q], wv[q], s);
            #pragma unroll
            for (int off = 16; off > 0; off >>= 1) s += __shfl_xor_sync(FULLM, s, off);
            if (lane == 0) ovs[w*4 + pp][o] = s;
        }
    }
    __syncthreads();

    for (int idx = t; idx < 288; idx += 256) {
        const int pl = idx / 9, a = idx % 9;
        const int pos = grp*32 + pl;
        const int i = pos >> 4, j = pos & 15;
        const float xc = (j + 0.5f) * 16.f, yc = (i + 0.5f) * 16.f;
        const float aw = c_AW[a], ah = c_AH[a];
        const float logit = ovs[pl][a] + cls_b[a];
        const float r0 = ovs[pl][9 + a*4 + 0] + reg_b[a*4 + 0];
        const float r1 = ovs[pl][9 + a*4 + 1] + reg_b[a*4 + 1];
        const float r2 = ovs[pl][9 + a*4 + 2] + reg_b[a*4 + 2];
        const float r3 = ovs[pl][9 + a*4 + 3] + reg_b[a*4 + 3];
        const float cx = r0*aw + xc, cy = r1*ah + yc;
        const float pw = expf(r2)*aw, ph = expf(r3)*ah;
        float x1 = fminf(fmaxf(cx - 0.5f*pw, 0.f), 256.f);
        float y1 = fminf(fmaxf(cy - 0.5f*ph, 0.f), 256.f);
        float x2 = fminf(fmaxf(cx + 0.5f*pw, 0.f), 256.f);
        float y2 = fminf(fmaxf(cy + 0.5f*ph, 0.f), 256.f);
        if (x2 - x1 < 1.f) x2 = x1 + 1.f;
        if (y2 - y1 < 1.f) y2 = y1 + 1.f;
        const int ai = pos*9 + a;
        g_scores[b*NANCH + ai] = 1.f / (1.f + expf(-logit));
        float* bp = &g_boxes[((size_t)b*NANCH + ai)*4];
        bp[0] = x1; bp[1] = y1; bp[2] = x2; bp[3] = y2;
    }
}

// ---------------- 3. per-batch top-30 (stable) + sequential NMS -----------------
__global__ __launch_bounds__(256) void topk_nms_kernel() {
    const int b = blockIdx.x, t = threadIdx.x;
    __shared__ float sc[NANCH];
    __shared__ float rv[256];
    __shared__ int   ri[256];
    __shared__ int   sel[KTOP];
    __shared__ float bx[KTOP][4];
    __shared__ int   keep[KTOP];
    for (int k = t; k < NANCH; k += 256) sc[k] = g_scores[b*NANCH + k];
    __syncthreads();
    for (int it = 0; it < KTOP; it++) {
        float bv = -3.f; int bi = NANCH;
        for (int k = t; k < NANCH; k += 256) {
            const float v = sc[k];
            if (v > bv || (v == bv && k < bi)) { bv = v; bi = k; }
        }
        rv[t] = bv; ri[t] = bi;
        __syncthreads();
        for (int s = 128; s > 0; s >>= 1) {
            if (t < s) {
                const float v2 = rv[t + s]; const int i2 = ri[t + s];
                if (v2 > rv[t] || (v2 == rv[t] && i2 < ri[t])) { rv[t] = v2; ri[t] = i2; }
            }
            __syncthreads();
        }
        if (t == 0) { sel[it] = ri[0]; sc[ri[0]] = -2.f; }
        __syncthreads();
    }
    if (t < KTOP) {
        const float* bp = &g_boxes[((size_t)b*NANCH + sel[t])*4];
        bx[t][0] = bp[0]; bx[t][1] = bp[1]; bx[t][2] = bp[2]; bx[t][3] = bp[3];
        keep[t] = 1;
    }
    __syncthreads();
    for (int ii = 0; ii < KTOP; ii++) {
        if (t < KTOP && t > ii && keep[ii]) {
            const float ax1 = bx[ii][0], ay1 = bx[ii][1], ax2 = bx[ii][2], ay2 = bx[ii][3];
            const float bx1 = bx[t][0], by1 = bx[t][1], bx2 = bx[t][2], by2 = bx[t][3];
            const float areaA = (ax2 - ax1) * (ay2 - ay1);
            const float areaB = (bx2 - bx1) * (by2 - by1);
            const float iw = fmaxf(fminf(ax2, bx2) - fmaxf(ax1, bx1), 0.f);
            const float ih = fmaxf(fminf(ay2, by2) - fmaxf(ay1, by1), 0.f);
            const float inter = iw * ih;
            const float iou = inter / (areaA + areaB - inter);
            if (iou > 0.85f) keep[t] = 0;
        }
        __syncthreads();
    }
    if (t < KTOP) {
        const int r = b*KTOP + t;
        g_rois[r*4 + 0] = bx[t][0];
        g_rois[r*4 + 1] = bx[t][1];
        g_rois[r*4 + 2] = bx[t][2];
        g_rois[r*4 + 3] = bx[t][3];
        g_valid[r] = keep[t];
    }
}

// ---------------- 4. integral image: warp-scan rows, tiled column scan ----------
__global__ __launch_bounds__(256) void integral_rows(const float* __restrict__ gt) {
    const int b = blockIdx.y, t = threadIdx.x;
    const int w = t >> 5, lane = t & 31;
    const int row = blockIdx.x * 8 + w;
    if (blockIdx.x == 0) {
        for (int idx = t; idx < 257; idx += 256)
            g_integral[((size_t)b*257)*257 + idx] = 0.f;
    }
    const float* gr = gt + (size_t)b*65536 + (size_t)row*256;
    float* Ir = g_integral + ((size_t)b*257 + row + 1)*257;
    if (lane == 0) Ir[0] = 0.f;
    float carry = 0.f;
    #pragma unroll
    for (int chunk = 0; chunk < 8; chunk++) {
        float v = gr[chunk*32 + lane];
        #pragma unroll
        for (int off = 1; off < 32; off <<= 1) {
            const float n = __shfl_up_sync(FULLM, v, off);
            if (lane >= off) v += n;
        }
        Ir[1 + chunk*32 + lane] = carry + v;
        carry += __shfl_sync(FULLM, v, 31);
    }
}

__global__ __launch_bounds__(256) void integral_cols() {
    __shared__ float tile[32][264];
    const int b = blockIdx.x, t = threadIdx.x;
    float* base = &g_integral[(size_t)b*257*257];
    float s0 = 0.f, s1 = 0.f;
    for (int ti = 0; ti < 8; ti++) {
        const int r0 = ti*32 + 1;
        #pragma unroll 4
        for (int rr = 0; rr < 32; rr++) {
            tile[rr][t] = base[(size_t)(r0 + rr)*257 + t];
            if (t == 0) tile[rr][256] = base[(size_t)(r0 + rr)*257 + 256];
        }
        __syncthreads();
        #pragma unroll 4
        for (int rr = 0; rr < 32; rr++) {
            s0 += tile[rr][t];  tile[rr][t] = s0;
            if (t == 0) { s1 += tile[rr][256]; tile[rr][256] = s1; }
        }
        __syncthreads();
        #pragma unroll 4
        for (int rr = 0; rr < 32; rr++) {
            base[(size_t)(r0 + rr)*257 + t] = tile[rr][t];
            if (t == 0) base[(size_t)(r0 + rr)*257 + 256] = tile[rr][256];
        }
        __syncthreads();
    }
}

// ---------------- 5. ROI-align mean (1024 ch, float4) + label -------------------
__global__ __launch_bounds__(256) void roialign_kernel(const float* __restrict__ clip) {
    const int r = blockIdx.x, t = threadIdx.x;
    const int b = r / KTOP;
    __shared__ int   o00[49], o01[49], o10[49], o11[49];
    __shared__ float w00[49], w01[49], w10[49], w11[49];
    __shared__ float roi[4];
    if (t < 4) roi[t] = g_rois[r*4 + t];
    __syncthreads();
    if (t == 0) {
        const int x1 = min(max((int)roi[0], 0), 256);
        const int y1 = min(max((int)roi[1], 0), 256);
        const int x2 = min(max((int)roi[2], 0), 256);
        const int y2 = min(max((int)roi[3], 0), 256);
        const float* I = &g_integral[(size_t)b*257*257];
        const float sI = I[y2*257 + x2] - I[y1*257 + x2] - I[y2*257 + x1] + I[y1*257 + x1];
        const int cnt = (y2 - y1) * (x2 - x1);
        g_labels[r] = (cnt > 0) && (sI / (float)max(cnt, 1) > 0.5f) ? 1 : 0;
    }
    if (!g_valid[r]) return;
    if (t < 49) {
        const int py = t / 7, px = t % 7;
        const float sc = 1.f / 16.f;
        const float x1f = roi[0]*sc, y1f = roi[1]*sc;
        const float rw = fmaxf(roi[2]*sc - x1f, 1.f);
        const float rh = fmaxf(roi[3]*sc - y1f, 1.f);
        const float X = x1f + (px + 0.5f) * (rw / 7.f);
        const float Y = y1f + (py + 0.5f) * (rh / 7.f);
        const bool ok = (Y > -1.f) && (Y < 16.f) && (X > -1.f) && (X < 16.f);
        const float Xc = fminf(fmaxf(X, 0.f), 15.f);
        const float Yc = fminf(fmaxf(Y, 0.f), 15.f);
        const int x0 = (int)floorf(Xc), y0 = (int)floorf(Yc);
        const int x1i = min(x0 + 1, 15), y1i = min(y0 + 1, 15);
        const float lx = Xc - (float)x0, ly = Yc - (float)y0;
        const float hx = 1.f - lx, hy = 1.f - ly;
        const float okf = ok ? 1.f : 0.f;
        o00[t] = (1 + y0*16  + x0 )*8192 + b*256;
        o01[t] = (1 + y0*16  + x1i)*8192 + b*256;
        o10[t] = (1 + y1i*16 + x0 )*8192 + b*256;
        o11[t] = (1 + y1i*16 + x1i)*8192 + b*256;
        w00[t] = hy*hx*okf; w01[t] = hy*lx*okf; w10[t] = ly*hx*okf; w11[t] = ly*lx*okf;
    }
    __syncthreads();
    const float4* clip4 = (const float4*)clip;
    float4 s = make_float4(0.f, 0.f, 0.f, 0.f);
    for (int p = 0; p < 49; p++) {
        const float4 a = clip4[o00[p] + t];
        const float4 bb = clip4[o01[p] + t];
        const float4 c = clip4[o10[p] + t];
        const float4 d = clip4[o11[p] + t];
        const float wa = w00[p], wb = w01[p], wc = w10[p], wd = w11[p];
        s.x += wa*a.x + wb*bb.x + wc*c.x + wd*d.x;
        s.y += wa*a.y + wb*bb.y + wc*c.y + wd*d.y;
        s.z += wa*a.z + wb*bb.z + wc*c.z + wd*d.z;
        s.w += wa*a.w + wb*bb.w + wc*c.w + wd*d.w;
    }
    const float inv = 1.f/49.f;
    float4* po = (float4*)&g_pooled[(size_t)r*1024];
    po[t] = make_float4(s.x*inv, s.y*inv, s.z*inv, s.w*inv);
}

// ---------------- 6. projection MLP, 4 ROIs per block, warp-per-output ----------
#define RPB 4
__global__ __launch_bounds__(256) void mlp_kernel(const float* __restrict__ w1,
                                                  const float* __restrict__ b1,
                                                  const float* __restrict__ w2,
                                                  const float* __restrict__ b2) {
    const int r0 = blockIdx.x * RPB, t = threadIdx.x;
    const int w = t >> 5, lane = t & 31;
    if (!(g_valid[r0] | g_valid[r0+1] | g_valid[r0+2] | g_valid[r0+3])) return;
    __shared__ float pr[RPB][1024];
    __shared__ float hs[RPB][256];
    __shared__ float ps[RPB][256];
    __shared__ float dn[RPB];
    for (int idx = t; idx < RPB*1024; idx += 256)
        pr[idx >> 10][idx & 1023] = g_pooled[(size_t)r0*1024 + idx];
    __syncthreads();
    for (int m = 0; m < 32; m++) {
        const int o = m*8 + w;
        float a0 = 0.f, a1 = 0.f, a2 = 0.f, a3 = 0.f;
        const float* wr = w1 + (size_t)o*1024;
        #pragma unroll 8
        for (int q = 0; q < 32; q++) {
            const float wv = wr[q*32 + lane];
            a0 = fmaf(wv, pr[0][q*32 + lane], a0);
            a1 = fmaf(wv, pr[1][q*32 + lane], a1);
            a2 = fmaf(wv, pr[2][q*32 + lane], a2);
            a3 = fmaf(wv, pr[3][q*32 + lane], a3);
        }
        #pragma unroll
        for (int off = 16; off > 0; off >>= 1) {
            a0 += __shfl_xor_sync(FULLM, a0, off);
            a1 += __shfl_xor_sync(FULLM, a1, off);
            a2 += __shfl_xor_sync(FULLM, a2, off);
            a3 += __shfl_xor_sync(FULLM, a3, off);
        }
        if (lane == 0) {
            const float bb = b1[o];
            hs[0][o] = fmaxf(a0 + bb, 0.f);
            hs[1][o] = fmaxf(a1 + bb, 0.f);
            hs[2][o] = fmaxf(a2 + bb, 0.f);
            hs[3][o] = fmaxf(a3 + bb, 0.f);
        }
    }
    __syncthreads();
    for (int m = 0; m < 32; m++) {
        const int o = m*8 + w;
        float a0 = 0.f, a1 = 0.f, a2 = 0.f, a3 = 0.f;
        const float* wr = w2 + (size_t)o*256;
        #pragma unroll
        for (int q = 0; q < 8; q++) {
            const float wv = wr[q*32 + lane];
            a0 = fmaf(wv, hs[0][q*32 + lane], a0);
            a1 = fmaf(wv, hs[1][q*32 + lane], a1);
            a2 = fmaf(wv, hs[2][q*32 + lane], a2);
            a3 = fmaf(wv, hs[3][q*32 + lane], a3);
        }
        #pragma unroll
        for (int off = 16; off > 0; off >>= 1) {
            a0 += __shfl_xor_sync(FULLM, a0, off);
            a1 += __shfl_xor_sync(FULLM, a1, off);
            a2 += __shfl_xor_sync(FULLM, a2, off);
            a3 += __shfl_xor_sync(FULLM, a3, off);
        }
        if (lane == 0) {
            const float bb = b2[o];
            ps[0][o] = a0 + bb; ps[1][o] = a1 + bb;
            ps[2][o] = a2 + bb; ps[3][o] = a3 + bb;
        }
    }
    __syncthreads();
    if (w < RPB) {
        float ss = 0.f;
        #pragma unroll
        for (int q = 0; q < 8; q++) {
            const float v = ps[w][q*32 + lane];
            ss = fmaf(v, v, ss);
        }
        #pragma unroll
        for (int off = 16; off > 0; off >>= 1) ss += __shfl_xor_sync(FULLM, ss, off);
        if (lane == 0) dn[w] = fmaxf(sqrtf(ss), 1e-12f);
    }
    __syncthreads();
    for (int idx = t; idx < RPB*256; idx += 256) {
        const int r = idx >> 8, o = idx & 255;
        g_proj[(size_t)(r0 + r)*256 + o] = ps[r][o] / dn[r];
    }
}

// ---------------- 7. SupCon loss, 4 anchors per block, warp-per-j ---------------
#define IPB 4
__global__ __launch_bounds__(256) void supcon_kernel() {
    const int i0 = blockIdx.x * IPB, t = threadIdx.x;
    const int w = t >> 5, lane = t & 31;
    __shared__ float nfi[IPB][256];
    __shared__ int   jv[NROI];
    __shared__ int   jl[NROI];
    __shared__ float w_ps[8][IPB], w_ds[8][IPB];
    __shared__ int   w_pc[8][IPB];
    for (int idx = t; idx < IPB*256; idx += 256)
        nfi[idx >> 8][idx & 255] = g_proj[(size_t)i0*256 + idx];
    for (int idx = t; idx < NROI; idx += 256) { jv[idx] = g_valid[idx]; jl[idx] = g_labels[idx]; }
    __syncthreads();

    int li[IPB];
    #pragma unroll
    for (int i = 0; i < IPB; i++) li[i] = jl[i0 + i];

    float ps[IPB] = {0.f, 0.f, 0.f, 0.f};
    float ds[IPB] = {0.f, 0.f, 0.f, 0.f};
    int   pc[IPB] = {0, 0, 0, 0};

    for (int j = w; j < NROI; j += 8) {
        if (!jv[j]) continue;
        const float* pj = &g_proj[(size_t)j*256];
        float d0 = 0.f, d1 = 0.f, d2 = 0.f, d3 = 0.f;
        #pragma unroll
        for (int q = 0; q < 8; q++) {
            const float v = pj[q*32 + lane];
            d0 = fmaf(v, nfi[0][q*32 + lane], d0);
            d1 = fmaf(v, nfi[1][q*32 + lane], d1);
            d2 = fmaf(v, nfi[2][q*32 + lane], d2);
            d3 = fmaf(v, nfi[3][q*32 + lane], d3);
        }
        #pragma unroll
        for (int off = 16; off > 0; off >>= 1) {
            d0 += __shfl_xor_sync(FULLM, d0, off);
            d1 += __shfl_xor_sync(FULLM, d1, off);
            d2 += __shfl_xor_sync(FULLM, d2, off);
            d3 += __shfl_xor_sync(FULLM, d3, off);
        }
        const int lj = jl[j];
        float dd[IPB] = {d0, d1, d2, d3};
        #pragma unroll
        for (int i = 0; i < IPB; i++) {
            if (j == i0 + i) continue;
            const float es = expf(dd[i] / 0.07f);
            ds[i] += es;
            if (lj == li[i]) { ps[i] += es; pc[i]++; }
        }
    }
    if (lane == 0) {
        #pragma unroll
        for (int i = 0; i < IPB; i++) { w_ps[w][i] = ps[i]; w_ds[w][i] = ds[i]; w_pc[w][i] = pc[i]; }
    }
    __syncthreads();
    if (t < IPB) {
        float P = 0.f, D = 0.f; int C = 0;
        #pragma unroll
        for (int ww = 0; ww < 8; ww++) { P += w_ps[ww][t]; D += w_ds[ww][t]; C += w_pc[ww][t]; }
        const float ratio = P / (D + 1e-12f);
        const float l = -logf(ratio + 1e-12f);
        const int act = jv[i0 + t] && (C > 0);
        g_li[i0 + t] = act ? l : 0.f;
        g_active[i0 + t] = act;
    }
}

// ---------------- 8. final reduction --------------------------------------------
__global__ __launch_bounds__(256) void final_kernel(float* __restrict__ out) {
    const int t = threadIdx.x;
    __shared__ float rs[256];
    __shared__ int   rc[256];
    float s = 0.f; int c = 0;
    for (int k = t; k < NROI; k += 256) { s += g_li[k]; c += g_active[k]; }
    rs[t] = s; rc[t] = c;
    __syncthreads();
    for (int st = 128; st > 0; st >>= 1) {
        if (t < st) { rs[t] += rs[t + st]; rc[t] += rc[t + st]; }
        __syncthreads();
    }
    if (t == 0) out[0] = (rc[0] > 0) ? rs[0] / (float)max(rc[0], 1) : 0.f;
}

// ---------------- launch --------------------------------------------------------
extern "C" void kernel_launch(void* const* d_in, const int* in_sizes, int n_in,
                              void* d_out, int out_size) {
    const float* clip   = (const float*)d_in[0];
    const float* gt     = (const float*)d_in[1];
    const float* conv_w = (const float*)d_in[2];
    const float* conv_b = (const float*)d_in[3];
    const float* cls_w  = (const float*)d_in[4];
    const float* cls_b  = (const float*)d_in[5];
    const float* reg_w  = (const float*)d_in[6];
    const float* reg_b  = (const float*)d_in[7];
    const float* w1     = (const float*)d_in[8];
    const float* b1     = (const float*)d_in[9];
    const float* w2     = (const float*)d_in[10];
    const float* b2     = (const float*)d_in[11];
    float* out = (float*)d_out;

    const int head_smem = 45*512*sizeof(float);   // 92160 B
    cudaFuncSetAttribute(head_kernel, cudaFuncAttributeMaxDynamicSharedMemorySize, head_smem);
    cudaFuncSetAttribute(conv_mma_kernel, cudaFuncAttributeMaxDynamicSharedMemorySize, CONV_SMEM);

    split_act<<<8192, 256>>>(clip);                 // 32*256*1024/4/256
    split_w<<<18432, 256>>>(conv_w);                // 9*512*1024/256
    conv_mma_kernel<<<dim3(8, 32), 256, CONV_SMEM>>>(conv_b);
    integral_rows<<<dim3(32, 32), 256>>>(gt);
    integral_cols<<<32, 256>>>();
    head_kernel<<<dim3(8, 32), 256, head_smem>>>(cls_w, cls_b, reg_w, reg_b);
    topk_nms_kernel<<<32, 256>>>();
    roialign_kernel<<<NROI, 256>>>(clip);
    mlp_kernel<<<NROI/RPB, 256>>>(w1, b1, w2, b2);
    supcon_kernel<<<NROI/IPB, 256>>>();
    final_kernel<<<1, 256>>>(out);
}

// round 13
// speedup vs baseline: 1.6219x; 1.6219x over previous
#include <cuda_runtime.h>
#include <cuda_bf16.h>
#include <math.h>

#define BNUM 32
#define CLIPD 1024
#define OCN 512
#define KTOP 30
#define NROI (BNUM*KTOP)     // 960
#define NANCH 2304           // 16*16*9
#define FULLM 0xFFFFFFFFu

// ---------------- scratch (static device globals; no runtime alloc) -------------
__device__ float g_x[BNUM*256*OCN];          // conv output, layout [b*256+pos][oc]
__device__ float g_scores[BNUM*NANCH];
__device__ float g_boxes[BNUM*NANCH*4];
__device__ float g_rois[NROI*4];
__device__ int   g_valid[NROI];
__device__ float g_integral[BNUM*257*257];
__device__ int   g_labels[NROI];
__device__ float g_pooled[NROI*CLIPD];
__device__ float g_proj[NROI*256];
__device__ float g_li[NROI];
__device__ int   g_active[NROI];

// bf16 3-way splits of activations [b][pos][c] and weights [tap][oc][c]
__device__ __align__(16) unsigned short g_a0[BNUM*256*1024];
__device__ __align__(16) unsigned short g_a1[BNUM*256*1024];
__device__ __align__(16) unsigned short g_a2[BNUM*256*1024];
__device__ __align__(16) unsigned short g_w0[9*512*1024];
__device__ __align__(16) unsigned short g_w1[9*512*1024];
__device__ __align__(16) unsigned short g_w2[9*512*1024];

// anchor w/h for a = si*3+ri, scales {8,16,32}, ratios {0.5,1,2}
__constant__ float c_AW[9] = {5.656854249492381f, 8.f, 11.313708498984761f,
                              11.313708498984761f, 16.f, 22.627416997969522f,
                              22.627416997969522f, 32.f, 45.254833995939045f};
__constant__ float c_AH[9] = {11.313708498984761f, 8.f, 5.656854249492381f,
                              22.627416997969522f, 16.f, 11.313708498984761f,
                              45.254833995939045f, 32.f, 22.627416997969522f};

// ================= warp-level tensor core helpers (baseline PTX, sm_80+) =========
__device__ __forceinline__ unsigned smem_u32(const void* p) {
    unsigned a;
    asm("{ .reg .u64 tmp; cvta.to.shared.u64 tmp, %1; cvt.u32.u64 %0, tmp; }"
        : "=r"(a) : "l"(p));
    return a;
}
__device__ __forceinline__ void ldsm4(unsigned* r, unsigned addr) {
    asm volatile("ldmatrix.sync.aligned.m8n8.x4.shared.b16 {%0,%1,%2,%3}, [%4];"
        : "=r"(r[0]), "=r"(r[1]), "=r"(r[2]), "=r"(r[3]) : "r"(addr));
}
__device__ __forceinline__ void mma16816(float* d, const unsigned* a, const unsigned* b) {
    asm volatile(
        "mma.sync.aligned.m16n8k16.row.col.f32.bf16.bf16.f32 "
        "{%0,%1,%2,%3}, {%4,%5,%6,%7}, {%8,%9}, {%0,%1,%2,%3};"
        : "+f"(d[0]), "+f"(d[1]), "+f"(d[2]), "+f"(d[3])
        : "r"(a[0]), "r"(a[1]), "r"(a[2]), "r"(a[3]), "r"(b[0]), "r"(b[1]));
}
__device__ __forceinline__ void cpa16(unsigned dst, const void* src) {
    asm volatile("cp.async.cg.shared.global [%0], [%1], 16;" :: "r"(dst), "l"(src));
}
__device__ __forceinline__ void cpa_commit() {
    asm volatile("cp.async.commit_group;" ::: "memory");
}
__device__ __forceinline__ void cpa_wait0() {
    asm volatile("cp.async.wait_group 0;" ::: "memory");
}

// ---------------- 0a. split activations fp32 -> 3x bf16 -------------------------
__device__ __forceinline__ void bsplit(float v, unsigned short& s0,
                                       unsigned short& s1, unsigned short& s2) {
    __nv_bfloat16 b0 = __float2bfloat16(v);
    float r = v - __bfloat162float(b0);
    __nv_bfloat16 b1 = __float2bfloat16(r);
    float r2 = r - __bfloat162float(b1);
    __nv_bfloat16 b2 = __float2bfloat16(r2);
    s0 = __bfloat16_as_ushort(b0);
    s1 = __bfloat16_as_ushort(b1);
    s2 = __bfloat16_as_ushort(b2);
}

__global__ __launch_bounds__(256) void split_act(const float* __restrict__ clip) {
    const size_t idx = (size_t)blockIdx.x * 256 + threadIdx.x;   // float4 index
    const size_t e = idx * 4;
    const int c4 = (int)(e & 1023);
    const int bp = (int)(e >> 10);
    const int b = bp >> 8, pos = bp & 255;
    const float4 v = *(const float4*)(clip + (size_t)(1 + pos)*32768 + b*1024 + c4);
    ushort4 u0, u1, u2;
    bsplit(v.x, u0.x, u1.x, u2.x);
    bsplit(v.y, u0.y, u1.y, u2.y);
    bsplit(v.z, u0.z, u1.z, u2.z);
    bsplit(v.w, u0.w, u1.w, u2.w);
    *(ushort4*)(g_a0 + e) = u0;
    *(ushort4*)(g_a1 + e) = u1;
    *(ushort4*)(g_a2 + e) = u2;
}

// ---------------- 0b. split weights [oc][c][tap] -> 3x bf16 [tap][oc][c] --------
__global__ __launch_bounds__(256) void split_w(const float* __restrict__ W) {
    const size_t idx = (size_t)blockIdx.x * 256 + threadIdx.x;   // [tap][oc][c]
    const int c = (int)(idx & 1023);
    const int oc = (int)((idx >> 10) & 511);
    const int tap = (int)(idx >> 19);
    const float v = W[((size_t)oc*1024 + c)*9 + tap];
    unsigned short s0, s1, s2;
    bsplit(v, s0, s1, s2);
    g_w0[idx] = s0; g_w1[idx] = s1; g_w2[idx] = s2;
}

// ---------------- 1. conv as implicit GEMM via mma.sync (bf16x3 split) ----------
// grid (8, 32): x = mh*4 + nt, y = b. CTA = 128 pos x 128 oc.
// 8 warps in 2x4; each warp owns 64x32 = 4x4 m16n8 tiles.
// A staged as 10x18 position halo per 32-channel chunk; halo borders zeroed ONCE.
// B double-buffered and prefetched via cp.async during MMA compute -> 1 sync/tap.
// smem rows stride 80B -> conflict-free LDSM.
#define SA_SZ   (180*80)                 // 14400 B per split
#define SB_OFF  (3*SA_SZ)                // 43200
#define SB_SZ   (128*80)                 // 10240 B per split
#define SB_BUF  (3*SB_SZ)                // 30720 B per buffer
#define CONV_SMEM (SB_OFF + 2*SB_BUF)    // 104640 B

__global__ __launch_bounds__(256, 2) void conv_mma_kernel(const float* __restrict__ bias) {
    extern __shared__ char cms[];
    const unsigned sbase = smem_u32(cms);
    const int t = threadIdx.x, lane = t & 31, wid = t >> 5;
    const int mh = blockIdx.x >> 2, nt = blockIdx.x & 3;
    const int b = blockIdx.y;
    const int wm = wid >> 2, wn = wid & 3;   // warps 2 (m) x 4 (n)
    const int R0 = mh * 8;                   // first image row of this half

    const unsigned short* AP[3] = {g_a0, g_a1, g_a2};
    const unsigned short* WP[3] = {g_w0, g_w1, g_w2};

    float acc[4][4][4];
    #pragma unroll
    for (int mt = 0; mt < 4; mt++)
        #pragma unroll
        for (int n = 0; n < 4; n++)
            #pragma unroll
            for (int q = 0; q < 4; q++) acc[mt][n][q] = 0.f;

    // per-lane ldmatrix geometry
    const int rw    = lane & 7;
    const int aRow8 = (lane >> 3) & 1;       // A: sel&1 -> +8 rows
    const int aK8   = lane >> 4;             // A: sel>>1 -> +8 k
    int lrA[4], lcA[4];                      // image row/col of this lane's A row
    #pragma unroll
    for (int mt = 0; mt < 4; mt++) {
        const int p = wm*64 + mt*16 + aRow8*8 + rw;
        lrA[mt] = p >> 4; lcA[mt] = p & 15;
    }
    const int bK8  = (lane >> 3) & 1;        // B: sel&1 -> +8 k
    const int bN8  = (lane >> 4);            // B: sel>>1 -> +8 n rows
    const unsigned bRowAddr = (unsigned)((wn*32 + bN8*8 + rw)*80 + bK8*16);

    // zero entire A halo region once (borders persist as zeros; interior
    // overwritten per channel-chunk by cp.async)
    for (int idx = t; idx < SB_OFF/16; idx += 256)
        *(uint4*)(cms + idx*16) = make_uint4(0u, 0u, 0u, 0u);
    __syncthreads();

    const int vr0 = (mh == 0) ? 1 : 0;       // first valid halo row

    // ---- staging helpers (cp.async, non-blocking) ----
    #define STAGE_B(tapv, cbv, bufv)                                              \
        do {                                                                      \
            const int _c0 = (cbv)*32;                                             \
            for (int idx = t; idx < 1536; idx += 256) {                           \
                const int s = idx >> 9, rem = idx & 511;                          \
                const int row = rem >> 2, q = rem & 3;                            \
                cpa16(sbase + SB_OFF + (bufv)*SB_BUF + s*SB_SZ + row*80 + q*16,   \
                      WP[s] + ((size_t)((tapv)*512 + nt*128 + row)*1024 + _c0 + q*8)); \
            }                                                                     \
        } while (0)

    #define STAGE_A(cbv)                                                          \
        do {                                                                      \
            const int _c0 = (cbv)*32;                                             \
            for (int idx = t; idx < 1728; idx += 256) {                           \
                const int s = idx / 576, rem = idx % 576;                         \
                const int cell = rem >> 2, q = rem & 3;                           \
                const int hr = vr0 + (cell >> 4), hc = 1 + (cell & 15);           \
                const int ir = R0 - 1 + hr, jc = hc - 1;                          \
                cpa16(sbase + s*SA_SZ + (hr*18 + hc)*80 + q*16,                   \
                      AP[s] + ((size_t)(b*256 + ir*16 + jc)*1024 + _c0 + q*8));   \
            }                                                                     \
        } while (0)

    // prologue: stage A(0) + B(tap0, cb0) into buffer 0
    STAGE_A(0);
    STAGE_B(0, 0, 0);
    cpa_commit();
    cpa_wait0();
    __syncthreads();

    int cur = 0;
    for (int cb = 0; cb < 32; cb++) {
        #pragma unroll 1
        for (int tap = 0; tap < 9; tap++) {
            const int di = tap/3 - 1, dj = tap%3 - 1;
            const int nxt = cur ^ 1;

            // prefetch next B while computing this tap
            if (tap < 8)            { STAGE_B(tap + 1, cb, nxt); cpa_commit(); }
            else if (cb < 31)       { STAGE_B(0, cb + 1, nxt);   cpa_commit(); }

            // A cell addresses for this tap (per m-tile)
            unsigned aAddr[4];
            #pragma unroll
            for (int mt = 0; mt < 4; mt++)
                aAddr[mt] = sbase +
                    (unsigned)(((lrA[mt] + di + 1)*18 + lcA[mt] + dj + 1)*80 + aK8*16);

            const unsigned bbase = sbase + SB_OFF + (unsigned)cur*SB_BUF + bRowAddr;

            // compute — accumulation order IDENTICAL to the passing round
            #pragma unroll
            for (int ks = 0; ks < 2; ks++) {
                const unsigned ko = (unsigned)(ks*32);
                #pragma unroll
                for (int s = 0; s < 3; s++) {
                    unsigned aF[4][4];
                    #pragma unroll
                    for (int mt = 0; mt < 4; mt++)
                        ldsm4(aF[mt], aAddr[mt] + s*SA_SZ + ko);
                    #pragma unroll
                    for (int tb = 0; tb < 3; tb++) {
                        if (s + tb >= 3) break;
                        unsigned bF[2][4];
                        #pragma unroll
                        for (int j = 0; j < 2; j++)
                            ldsm4(bF[j], bbase + (unsigned)(tb*SB_SZ) +
                                         (unsigned)(j*16*80) + ko);
                        #pragma unroll
                        for (int mt = 0; mt < 4; mt++)
                            #pragma unroll
                            for (int n = 0; n < 4; n++)
                                mma16816(acc[mt][n], aF[mt], &bF[n >> 1][(n & 1)*2]);
                    }
                }
            }

            if (tap == 8) {
                __syncthreads();               // all warps done reading A(cb)
                if (cb < 31) { STAGE_A(cb + 1); cpa_commit(); }
            }
            cpa_wait0();
            __syncthreads();
            cur = nxt;
        }
    }
    #undef STAGE_A
    #undef STAGE_B

    // epilogue: bias + relu + store
    const int g = lane >> 2, tg = lane & 3;
    #pragma unroll
    for (int mt = 0; mt < 4; mt++) {
        const int pos0 = mh*128 + wm*64 + mt*16 + g;
        #pragma unroll
        for (int n = 0; n < 4; n++) {
            const int oc = nt*128 + wn*32 + n*8 + tg*2;
            const float2 bb = *(const float2*)&bias[oc];
            float2 o0, o1;
            o0.x = fmaxf(acc[mt][n][0] + bb.x, 0.f);
            o0.y = fmaxf(acc[mt][n][1] + bb.y, 0.f);
            o1.x = fmaxf(acc[mt][n][2] + bb.x, 0.f);
            o1.y = fmaxf(acc[mt][n][3] + bb.y, 0.f);
            *(float2*)&g_x[((size_t)(b*256 + pos0    ))*512 + oc] = o0;
            *(float2*)&g_x[((size_t)(b*256 + pos0 + 8))*512 + oc] = o1;
        }
    }
}

// ---------------- 2. cls/reg heads + decode + sigmoid ---------------------------
extern __shared__ float s_hw[];   // [45][512]
__global__ __launch_bounds__(256) void head_kernel(const float* __restrict__ cls_w,
                                                   const float* __restrict__ cls_b,
                                                   const float* __restrict__ reg_w,
                                                   const float* __restrict__ reg_b) {
    const int b = blockIdx.y, grp = blockIdx.x;
    const int t = threadIdx.x, w = t >> 5, lane = t & 31;
    __shared__ float ovs[32][48];

    for (int idx = t; idx < 45*512; idx += 256) {
        const int o = idx >> 9, k = idx & 511;
        s_hw[idx] = (o < 9) ? cls_w[o*512 + k] : reg_w[(o - 9)*512 + k];
    }

    float xr[4][16];
    #pragma unroll
    for (int pp = 0; pp < 4; pp++) {
        const size_t row = (size_t)(b*256 + grp*32 + w*4 + pp);
        #pragma unroll
        for (int q = 0; q < 16; q++)
            xr[pp][q] = g_x[row*512 + q*32 + lane];
    }
    __syncthreads();

    for (int o = 0; o < 45; o++) {
        const float* wr = &s_hw[o*512];
        float wv[16];
        #pragma unroll
        for (int q = 0; q < 16; q++) wv[q] = wr[q*32 + lane];
        #pragma unroll
        for (int pp = 0; pp < 4; pp++) {
            float s = 0.f;
            #pragma unroll
            for (int q = 0; q < 16; q++) s = fmaf(xr[pp][q], wv[q], s);
            #pragma unroll
            for (int off = 16; off > 0; off >>= 1) s += __shfl_xor_sync(FULLM, s, off);
            if (lane == 0) ovs[w*4 + pp][o] = s;
        }
    }
    __syncthreads();

    for (int idx = t; idx < 288; idx += 256) {
        const int pl = idx / 9, a = idx % 9;
        const int pos = grp*32 + pl;
        const int i = pos >> 4, j = pos & 15;
        const float xc = (j + 0.5f) * 16.f, yc = (i + 0.5f) * 16.f;
        const float aw = c_AW[a], ah = c_AH[a];
        const float logit = ovs[pl][a] + cls_b[a];
        const float r0 = ovs[pl][9 + a*4 + 0] + reg_b[a*4 + 0];
        const float r1 = ovs[pl][9 + a*4 + 1] + reg_b[a*4 + 1];
        const float r2 = ovs[pl][9 + a*4 + 2] + reg_b[a*4 + 2];
        const float r3 = ovs[pl][9 + a*4 + 3] + reg_b[a*4 + 3];
        const float cx = r0*aw + xc, cy = r1*ah + yc;
        const float pw = expf(r2)*aw, ph = expf(r3)*ah;
        float x1 = fminf(fmaxf(cx - 0.5f*pw, 0.f), 256.f);
        float y1 = fminf(fmaxf(cy - 0.5f*ph, 0.f), 256.f);
        float x2 = fminf(fmaxf(cx + 0.5f*pw, 0.f), 256.f);
        float y2 = fminf(fmaxf(cy + 0.5f*ph, 0.f), 256.f);
        if (x2 - x1 < 1.f) x2 = x1 + 1.f;
        if (y2 - y1 < 1.f) y2 = y1 + 1.f;
        const int ai = pos*9 + a;
        g_scores[b*NANCH + ai] = 1.f / (1.f + expf(-logit));
        float* bp = &g_boxes[((size_t)b*NANCH + ai)*4];
        bp[0] = x1; bp[1] = y1; bp[2] = x2; bp[3] = y2;
    }
}

// ---------------- 3. per-batch top-30 (stable) + sequential NMS -----------------
__global__ __launch_bounds__(256) void topk_nms_kernel() {
    const int b = blockIdx.x, t = threadIdx.x;
    __shared__ float sc[NANCH];
    __shared__ float rv[256];
    __shared__ int   ri[256];
    __shared__ int   sel[KTOP];
    __shared__ float bx[KTOP][4];
    __shared__ int   keep[KTOP];
    for (int k = t; k < NANCH; k += 256) sc[k] = g_scores[b*NANCH + k];
    __syncthreads();
    for (int it = 0; it < KTOP; it++) {
        float bv = -3.f; int bi = NANCH;
        for (int k = t; k < NANCH; k += 256) {
            const float v = sc[k];
            if (v > bv || (v == bv && k < bi)) { bv = v; bi = k; }
        }
        rv[t] = bv; ri[t] = bi;
        __syncthreads();
        for (int s = 128; s > 0; s >>= 1) {
            if (t < s) {
                const float v2 = rv[t + s]; const int i2 = ri[t + s];
                if (v2 > rv[t] || (v2 == rv[t] && i2 < ri[t])) { rv[t] = v2; ri[t] = i2; }
            }
            __syncthreads();
        }
        if (t == 0) { sel[it] = ri[0]; sc[ri[0]] = -2.f; }
        __syncthreads();
    }
    if (t < KTOP) {
        const float* bp = &g_boxes[((size_t)b*NANCH + sel[t])*4];
        bx[t][0] = bp[0]; bx[t][1] = bp[1]; bx[t][2] = bp[2]; bx[t][3] = bp[3];
        keep[t] = 1;
    }
    __syncthreads();
    for (int ii = 0; ii < KTOP; ii++) {
        if (t < KTOP && t > ii && keep[ii]) {
            const float ax1 = bx[ii][0], ay1 = bx[ii][1], ax2 = bx[ii][2], ay2 = bx[ii][3];
            const float bx1 = bx[t][0], by1 = bx[t][1], bx2 = bx[t][2], by2 = bx[t][3];
            const float areaA = (ax2 - ax1) * (ay2 - ay1);
            const float areaB = (bx2 - bx1) * (by2 - by1);
            const float iw = fmaxf(fminf(ax2, bx2) - fmaxf(ax1, bx1), 0.f);
            const float ih = fmaxf(fminf(ay2, by2) - fmaxf(ay1, by1), 0.f);
            const float inter = iw * ih;
            const float iou = inter / (areaA + areaB - inter);
            if (iou > 0.85f) keep[t] = 0;
        }
        __syncthreads();
    }
    if (t < KTOP) {
        const int r = b*KTOP + t;
        g_rois[r*4 + 0] = bx[t][0];
        g_rois[r*4 + 1] = bx[t][1];
        g_rois[r*4 + 2] = bx[t][2];
        g_rois[r*4 + 3] = bx[t][3];
        g_valid[r] = keep[t];
    }
}

// ---------------- 4. integral image: warp-scan rows, tiled column scan ----------
__global__ __launch_bounds__(256) void integral_rows(const float* __restrict__ gt) {
    const int b = blockIdx.y, t = threadIdx.x;
    const int w = t >> 5, lane = t & 31;
    const int row = blockIdx.x * 8 + w;
    if (blockIdx.x == 0) {
        for (int idx = t; idx < 257; idx += 256)
            g_integral[((size_t)b*257)*257 + idx] = 0.f;
    }
    const float* gr = gt + (size_t)b*65536 + (size_t)row*256;
    float* Ir = g_integral + ((size_t)b*257 + row + 1)*257;
    if (lane == 0) Ir[0] = 0.f;
    float carry = 0.f;
    #pragma unroll
    for (int chunk = 0; chunk < 8; chunk++) {
        float v = gr[chunk*32 + lane];
        #pragma unroll
        for (int off = 1; off < 32; off <<= 1) {
            const float n = __shfl_up_sync(FULLM, v, off);
            if (lane >= off) v += n;
        }
        Ir[1 + chunk*32 + lane] = carry + v;
        carry += __shfl_sync(FULLM, v, 31);
    }
}

__global__ __launch_bounds__(256) void integral_cols() {
    __shared__ float tile[32][264];
    const int b = blockIdx.x, t = threadIdx.x;
    float* base = &g_integral[(size_t)b*257*257];
    float s0 = 0.f, s1 = 0.f;
    for (int ti = 0; ti < 8; ti++) {
        const int r0 = ti*32 + 1;
        #pragma unroll 4
        for (int rr = 0; rr < 32; rr++) {
            tile[rr][t] = base[(size_t)(r0 + rr)*257 + t];
            if (t == 0) tile[rr][256] = base[(size_t)(r0 + rr)*257 + 256];
        }
        __syncthreads();
        #pragma unroll 4
        for (int rr = 0; rr < 32; rr++) {
            s0 += tile[rr][t];  tile[rr][t] = s0;
            if (t == 0) { s1 += tile[rr][256]; tile[rr][256] = s1; }
        }
        __syncthreads();
        #pragma unroll 4
        for (int rr = 0; rr < 32; rr++) {
            base[(size_t)(r0 + rr)*257 + t] = tile[rr][t];
            if (t == 0) base[(size_t)(r0 + rr)*257 + 256] = tile[rr][256];
        }
        __syncthreads();
    }
}

// ---------------- 5. ROI-align mean (1024 ch, float4) + label -------------------
__global__ __launch_bounds__(256) void roialign_kernel(const float* __restrict__ clip) {
    const int r = blockIdx.x, t = threadIdx.x;
    const int b = r / KTOP;
    __shared__ int   o00[49], o01[49], o10[49], o11[49];
    __shared__ float w00[49], w01[49], w10[49], w11[49];
    __shared__ float roi[4];
    if (t < 4) roi[t] = g_rois[r*4 + t];
    __syncthreads();
    if (t == 0) {
        const int x1 = min(max((int)roi[0], 0), 256);
        const int y1 = min(max((int)roi[1], 0), 256);
        const int x2 = min(max((int)roi[2], 0), 256);
        const int y2 = min(max((int)roi[3], 0), 256);
        const float* I = &g_integral[(size_t)b*257*257];
        const float sI = I[y2*257 + x2] - I[y1*257 + x2] - I[y2*257 + x1] + I[y1*257 + x1];
        const int cnt = (y2 - y1) * (x2 - x1);
        g_labels[r] = (cnt > 0) && (sI / (float)max(cnt, 1) > 0.5f) ? 1 : 0;
    }
    if (!g_valid[r]) return;
    if (t < 49) {
        const int py = t / 7, px = t % 7;
        const float sc = 1.f / 16.f;
        const float x1f = roi[0]*sc, y1f = roi[1]*sc;
        const float rw = fmaxf(roi[2]*sc - x1f, 1.f);
        const float rh = fmaxf(roi[3]*sc - y1f, 1.f);
        const float X = x1f + (px + 0.5f) * (rw / 7.f);
        const float Y = y1f + (py + 0.5f) * (rh / 7.f);
        const bool ok = (Y > -1.f) && (Y < 16.f) && (X > -1.f) && (X < 16.f);
        const float Xc = fminf(fmaxf(X, 0.f), 15.f);
        const float Yc = fminf(fmaxf(Y, 0.f), 15.f);
        const int x0 = (int)floorf(Xc), y0 = (int)floorf(Yc);
        const int x1i = min(x0 + 1, 15), y1i = min(y0 + 1, 15);
        const float lx = Xc - (float)x0, ly = Yc - (float)y0;
        const float hx = 1.f - lx, hy = 1.f - ly;
        const float okf = ok ? 1.f : 0.f;
        o00[t] = (1 + y0*16  + x0 )*8192 + b*256;
        o01[t] = (1 + y0*16  + x1i)*8192 + b*256;
        o10[t] = (1 + y1i*16 + x0 )*8192 + b*256;
        o11[t] = (1 + y1i*16 + x1i)*8192 + b*256;
        w00[t] = hy*hx*okf; w01[t] = hy*lx*okf; w10[t] = ly*hx*okf; w11[t] = ly*lx*okf;
    }
    __syncthreads();
    const float4* clip4 = (const float4*)clip;
    float4 s = make_float4(0.f, 0.f, 0.f, 0.f);
    for (int p = 0; p < 49; p++) {
        const float4 a = clip4[o00[p] + t];
        const float4 bb = clip4[o01[p] + t];
        const float4 c = clip4[o10[p] + t];
        const float4 d = clip4[o11[p] + t];
        const float wa = w00[p], wb = w01[p], wc = w10[p], wd = w11[p];
        s.x += wa*a.x + wb*bb.x + wc*c.x + wd*d.x;
        s.y += wa*a.y + wb*bb.y + wc*c.y + wd*d.y;
        s.z += wa*a.z + wb*bb.z + wc*c.z + wd*d.z;
        s.w += wa*a.w + wb*bb.w + wc*c.w + wd*d.w;
    }
    const float inv = 1.f/49.f;
    float4* po = (float4*)&g_pooled[(size_t)r*1024];
    po[t] = make_float4(s.x*inv, s.y*inv, s.z*inv, s.w*inv);
}

// ---------------- 6. projection MLP, 4 ROIs per block, warp-per-output ----------
#define RPB 4
__global__ __launch_bounds__(256) void mlp_kernel(const float* __restrict__ w1,
                                                  const float* __restrict__ b1,
                                                  const float* __restrict__ w2,
                                                  const float* __restrict__ b2) {
    const int r0 = blockIdx.x * RPB, t = threadIdx.x;
    const int w = t >> 5, lane = t & 31;
    if (!(g_valid[r0] | g_valid[r0+1] | g_valid[r0+2] | g_valid[r0+3])) return;
    __shared__ float pr[RPB][1024];
    __shared__ float hs[RPB][256];
    __shared__ float ps[RPB][256];
    __shared__ float dn[RPB];
    for (int idx = t; idx < RPB*1024; idx += 256)
        pr[idx >> 10][idx & 1023] = g_pooled[(size_t)r0*1024 + idx];
    __syncthreads();
    for (int m = 0; m < 32; m++) {
        const int o = m*8 + w;
        float a0 = 0.f, a1 = 0.f, a2 = 0.f, a3 = 0.f;
        const float* wr = w1 + (size_t)o*1024;
        #pragma unroll 8
        for (int q = 0; q < 32; q++) {
            const float wv = wr[q*32 + lane];
            a0 = fmaf(wv, pr[0][q*32 + lane], a0);
            a1 = fmaf(wv, pr[1][q*32 + lane], a1);
            a2 = fmaf(wv, pr[2][q*32 + lane], a2);
            a3 = fmaf(wv, pr[3][q*32 + lane], a3);
        }
        #pragma unroll
        for (int off = 16; off > 0; off >>= 1) {
            a0 += __shfl_xor_sync(FULLM, a0, off);
            a1 += __shfl_xor_sync(FULLM, a1, off);
            a2 += __shfl_xor_sync(FULLM, a2, off);
            a3 += __shfl_xor_sync(FULLM, a3, off);
        }
        if (lane == 0) {
            const float bb = b1[o];
            hs[0][o] = fmaxf(a0 + bb, 0.f);
            hs[1][o] = fmaxf(a1 + bb, 0.f);
            hs[2][o] = fmaxf(a2 + bb, 0.f);
            hs[3][o] = fmaxf(a3 + bb, 0.f);
        }
    }
    __syncthreads();
    for (int m = 0; m < 32; m++) {
        const int o = m*8 + w;
        float a0 = 0.f, a1 = 0.f, a2 = 0.f, a3 = 0.f;
        const float* wr = w2 + (size_t)o*256;
        #pragma unroll
        for (int q = 0; q < 8; q++) {
            const float wv = wr[q*32 + lane];
            a0 = fmaf(wv, hs[0][q*32 + lane], a0);
            a1 = fmaf(wv, hs[1][q*32 + lane], a1);
            a2 = fmaf(wv, hs[2][q*32 + lane], a2);
            a3 = fmaf(wv, hs[3][q*32 + lane], a3);
        }
        #pragma unroll
        for (int off = 16; off > 0; off >>= 1) {
            a0 += __shfl_xor_sync(FULLM, a0, off);
            a1 += __shfl_xor_sync(FULLM, a1, off);
            a2 += __shfl_xor_sync(FULLM, a2, off);
            a3 += __shfl_xor_sync(FULLM, a3, off);
        }
        if (lane == 0) {
            const float bb = b2[o];
            ps[0][o] = a0 + bb; ps[1][o] = a1 + bb;
            ps[2][o] = a2 + bb; ps[3][o] = a3 + bb;
        }
    }
    __syncthreads();
    if (w < RPB) {
        float ss = 0.f;
        #pragma unroll
        for (int q = 0; q < 8; q++) {
            const float v = ps[w][q*32 + lane];
            ss = fmaf(v, v, ss);
        }
        #pragma unroll
        for (int off = 16; off > 0; off >>= 1) ss += __shfl_xor_sync(FULLM, ss, off);
        if (lane == 0) dn[w] = fmaxf(sqrtf(ss), 1e-12f);
    }
    __syncthreads();
    for (int idx = t; idx < RPB*256; idx += 256) {
        const int r = idx >> 8, o = idx & 255;
        g_proj[(size_t)(r0 + r)*256 + o] = ps[r][o] / dn[r];
    }
}

// ---------------- 7. SupCon loss, 4 anchors per block, warp-per-j ---------------
#define IPB 4
__global__ __launch_bounds__(256) void supcon_kernel() {
    const int i0 = blockIdx.x * IPB, t = threadIdx.x;
    const int w = t >> 5, lane = t & 31;
    __shared__ float nfi[IPB][256];
    __shared__ int   jv[NROI];
    __shared__ int   jl[NROI];
    __shared__ float w_ps[8][IPB], w_ds[8][IPB];
    __shared__ int   w_pc[8][IPB];
    for (int idx = t; idx < IPB*256; idx += 256)
        nfi[idx >> 8][idx & 255] = g_proj[(size_t)i0*256 + idx];
    for (int idx = t; idx < NROI; idx += 256) { jv[idx] = g_valid[idx]; jl[idx] = g_labels[idx]; }
    __syncthreads();

    int li[IPB];
    #pragma unroll
    for (int i = 0; i < IPB; i++) li[i] = jl[i0 + i];

    float ps[IPB] = {0.f, 0.f, 0.f, 0.f};
    float ds[IPB] = {0.f, 0.f, 0.f, 0.f};
    int   pc[IPB] = {0, 0, 0, 0};

    for (int j = w; j < NROI; j += 8) {
        if (!jv[j]) continue;
        const float* pj = &g_proj[(size_t)j*256];
        float d0 = 0.f, d1 = 0.f, d2 = 0.f, d3 = 0.f;
        #pragma unroll
        for (int q = 0; q < 8; q++) {
            const float v = pj[q*32 + lane];
            d0 = fmaf(v, nfi[0][q*32 + lane], d0);
            d1 = fmaf(v, nfi[1][q*32 + lane], d1);
            d2 = fmaf(v, nfi[2][q*32 + lane], d2);
            d3 = fmaf(v, nfi[3][q*32 + lane], d3);
        }
        #pragma unroll
        for (int off = 16; off > 0; off >>= 1) {
            d0 += __shfl_xor_sync(FULLM, d0, off);
            d1 += __shfl_xor_sync(FULLM, d1, off);
            d2 += __shfl_xor_sync(FULLM, d2, off);
            d3 += __shfl_xor_sync(FULLM, d3, off);
        }
        const int lj = jl[j];
        float dd[IPB] = {d0, d1, d2, d3};
        #pragma unroll
        for (int i = 0; i < IPB; i++) {
            if (j == i0 + i) continue;
            const float es = expf(dd[i] / 0.07f);
            ds[i] += es;
            if (lj == li[i]) { ps[i] += es; pc[i]++; }
        }
    }
    if (lane == 0) {
        #pragma unroll
        for (int i = 0; i < IPB; i++) { w_ps[w][i] = ps[i]; w_ds[w][i] = ds[i]; w_pc[w][i] = pc[i]; }
    }
    __syncthreads();
    if (t < IPB) {
        float P = 0.f, D = 0.f; int C = 0;
        #pragma unroll
        for (int ww = 0; ww < 8; ww++) { P += w_ps[ww][t]; D += w_ds[ww][t]; C += w_pc[ww][t]; }
        const float ratio = P / (D + 1e-12f);
        const float l = -logf(ratio + 1e-12f);
        const int act = jv[i0 + t] && (C > 0);
        g_li[i0 + t] = act ? l : 0.f;
        g_active[i0 + t] = act;
    }
}

// ---------------- 8. final reduction --------------------------------------------
__global__ __launch_bounds__(256) void final_kernel(float* __restrict__ out) {
    const int t = threadIdx.x;
    __shared__ float rs[256];
    __shared__ int   rc[256];
    float s = 0.f; int c = 0;
    for (int k = t; k < NROI; k += 256) { s += g_li[k]; c += g_active[k]; }
    rs[t] = s; rc[t] = c;
    __syncthreads();
    for (int st = 128; st > 0; st >>= 1) {
        if (t < st) { rs[t] += rs[t + st]; rc[t] += rc[t + st]; }
        __syncthreads();
    }
    if (t == 0) out[0] = (rc[0] > 0) ? rs[0] / (float)max(rc[0], 1) : 0.f;
}

// ---------------- launch --------------------------------------------------------
extern "C" void kernel_launch(void* const* d_in, const int* in_sizes, int n_in,
                              void* d_out, int out_size) {
    const float* clip   = (const float*)d_in[0];
    const float* gt     = (const float*)d_in[1];
    const float* conv_w = (const float*)d_in[2];
    const float* conv_b = (const float*)d_in[3];
    const float* cls_w  = (const float*)d_in[4];
    const float* cls_b  = (const float*)d_in[5];
    const float* reg_w  = (const float*)d_in[6];
    const float* reg_b  = (const float*)d_in[7];
    const float* w1     = (const float*)d_in[8];
    const float* b1     = (const float*)d_in[9];
    const float* w2     = (const float*)d_in[10];
    const float* b2     = (const float*)d_in[11];
    float* out = (float*)d_out;

    const int head_smem = 45*512*sizeof(float);   // 92160 B
    cudaFuncSetAttribute(head_kernel, cudaFuncAttributeMaxDynamicSharedMemorySize, head_smem);
    cudaFuncSetAttribute(conv_mma_kernel, cudaFuncAttributeMaxDynamicSharedMemorySize, CONV_SMEM);

    split_act<<<8192, 256>>>(clip);                 // 32*256*1024/4/256
    split_w<<<18432, 256>>>(conv_w);                // 9*512*1024/256
    conv_mma_kernel<<<dim3(8, 32), 256, CONV_SMEM>>>(conv_b);
    integral_rows<<<dim3(32, 32), 256>>>(gt);
    integral_cols<<<32, 256>>>();
    head_kernel<<<dim3(8, 32), 256, head_smem>>>(cls_w, cls_b, reg_w, reg_b);
    topk_nms_kernel<<<32, 256>>>();
    roialign_kernel<<<NROI, 256>>>(clip);
    mlp_kernel<<<NROI/RPB, 256>>>(w1, b1, w2, b2);
    supcon_kernel<<<NROI/IPB, 256>>>();
    final_kernel<<<1, 256>>>(out);
}